// round 4
// baseline (speedup 1.0000x reference)
#include <cuda_runtime.h>

// out[i] = 2 * in[i], N = 100 floats (25 float4). Launch-latency-bound.
// Full warp of 32 lanes; lanes 25..31 clamp to element 24 and redundantly
// write the same value (deterministic), so SASS has zero predication.
// 2*v computed as v+v (bit-identical in fp32). Streaming store skips L2
// allocate bookkeeping; load stays default-cached so the input remains
// L2-resident across graph replays.
__global__ void __launch_bounds__(32, 1) mul2_kernel(const float4* __restrict__ in,
                                                     float4* __restrict__ out) {
    int i = threadIdx.x;
    i = (i < 25) ? i : 24;         // SEL, no branch
    float4 v = __ldg(&in[i]);
    v.x += v.x; v.y += v.y; v.z += v.z; v.w += v.w;
    asm volatile("st.global.cs.v4.f32 [%0], {%1, %2, %3, %4};"
                 :: "l"(&out[i]), "f"(v.x), "f"(v.y), "f"(v.z), "f"(v.w)
                 : "memory");
}

extern "C" void kernel_launch(void* const* d_in, const int* in_sizes, int n_in,
                              void* d_out, int out_size) {
    const float4* in = (const float4*)d_in[0];
    float4* out = (float4*)d_out;
    mul2_kernel<<<1, 32>>>(in, out);
}